// round 10
// baseline (speedup 1.0000x reference)
#include <cuda_runtime.h>
#include <cstdint>

// Sepconv: out[b,c,y,x] = sum_{i,j} in[b,c,5y+i,5x+j] * V[b,i,y,x] * H[b,j,y,x]
// B=8, C=3, F=5, HO=WO=256. HBM-bound: 184.6 MB compulsory traffic; measured
// chip ceiling for this stream mix is ~6.15 TB/s (path-independent across
// LDG / cp.async / TMA) -> ~30 us kernel floor, which R8/R9 already hit.
//
// R10 (final): full-row blocks (256 thr, 2048 blocks) to halve per-block
// fixed costs (mbarrier init, proxy fence, posting, cold-start wait), with
// 5120B TMA bulk extents. Same roofline-bound schedule as R8.

#define B_ 8
#define C_ 3
#define F_ 5
#define HO_ 256
#define WO_ 256
#define HI_ (HO_ * F_)
#define WI_ (WO_ * F_)

#define STRIP_W  (WO_ * F_)               // 1280 floats per input row
#define ROW_BYTES (STRIP_W * 4)           // 5120 B per bulk copy
#define TILE_FLOATS (F_ * STRIP_W)        // 6400 floats = 25.6 KB per strip
#define TILE_BYTES  (TILE_FLOATS * 4)     // 25600
#define NT 256

__device__ __forceinline__ void mbar_init(uint32_t mbar, uint32_t count) {
    asm volatile("mbarrier.init.shared.b64 [%0], %1;\n"
                 :: "r"(mbar), "r"(count) : "memory");
}
__device__ __forceinline__ void mbar_expect_tx(uint32_t mbar, uint32_t bytes) {
    asm volatile("mbarrier.arrive.expect_tx.shared.b64 _, [%0], %1;\n"
                 :: "r"(mbar), "r"(bytes) : "memory");
}
__device__ __forceinline__ void bulk_cp(uint32_t dst, const void* src,
                                        uint32_t bytes, uint32_t mbar) {
    asm volatile(
        "cp.async.bulk.shared::cta.global.mbarrier::complete_tx::bytes "
        "[%0], [%1], %2, [%3];\n"
        :: "r"(dst), "l"(src), "r"(bytes), "r"(mbar) : "memory");
}
__device__ __forceinline__ void mbar_wait(uint32_t mbar, uint32_t parity) {
    asm volatile(
        "{\n\t"
        ".reg .pred P;\n\t"
        "WAIT_%=:\n\t"
        "mbarrier.try_wait.parity.acquire.cta.shared::cta.b64 P, [%0], %1, 0x989680;\n\t"
        "@!P bra WAIT_%=;\n\t"
        "}"
        :: "r"(mbar), "r"(parity) : "memory");
}

__global__ __launch_bounds__(NT) void sepconv_tma10_kernel(
    const float* __restrict__ in,
    const float* __restrict__ V,
    const float* __restrict__ H,
    float* __restrict__ out)
{
    extern __shared__ __align__(16) float sdata[];            // C_*25.6 KB
    __shared__ __align__(8) unsigned long long mbar[C_];

    const int tid = threadIdx.x;          // 0..255 = output x
    const int y   = blockIdx.x & (HO_ - 1);
    const int b   = blockIdx.x >> 8;

    const uint32_t sdata_u = (uint32_t)__cvta_generic_to_shared(sdata);
    const uint32_t mbar_u  = (uint32_t)__cvta_generic_to_shared(mbar);

    if (tid == 0) {
#pragma unroll
        for (int c = 0; c < C_; c++)
            mbar_init(mbar_u + 8u * c, 1);
        asm volatile("fence.proxy.async.shared::cta;\n" ::: "memory");
    }
    __syncthreads();

    // Lanes 0..2 each post one channel's 5 bulk copies (5120 B extents).
    if (tid < C_) {
        const int c = tid;
        const long long base0 =
            ((long long)(b * C_) * HI_ + (long long)y * F_) * WI_;
        mbar_expect_tx(mbar_u + 8u * c, TILE_BYTES);
        const float* strip = in + base0 + (long long)c * HI_ * WI_;
        const uint32_t dst = sdata_u + (uint32_t)(c * TILE_BYTES);
#pragma unroll
        for (int r = 0; r < F_; r++)
            bulk_cp(dst + (uint32_t)(r * ROW_BYTES),
                    strip + r * WI_, ROW_BYTES, mbar_u + 8u * c);
    }

    // Weights for (b, y, x=tid): coalesced, overlap with TMA in flight.
    float v[F_], h[F_];
    {
        const int sb = (b * F_) * (HO_ * WO_) + y * WO_ + tid;
#pragma unroll
        for (int i = 0; i < F_; i++) {
            v[i] = V[sb + i * (HO_ * WO_)];
            h[i] = H[sb + i * (HO_ * WO_)];
        }
    }

#pragma unroll
    for (int c = 0; c < C_; c++) {
        mbar_wait(mbar_u + 8u * c, 0);            // acquire: strip c ready

        const float* s = sdata + c * TILE_FLOATS;
        float acc = 0.0f;
#pragma unroll
        for (int i = 0; i < F_; i++) {
            const float* row = s + i * STRIP_W + tid * F_;
            float rs = 0.0f;
#pragma unroll
            for (int j = 0; j < F_; j++)
                rs = fmaf(row[j], h[j], rs);
            acc = fmaf(rs, v[i], acc);
        }
        __stcs(out + ((b * C_ + c) * HO_ + y) * WO_ + tid, acc);
    }
}

extern "C" void kernel_launch(void* const* d_in, const int* in_sizes, int n_in,
                              void* d_out, int out_size)
{
    const float* in  = (const float*)d_in[0];  // [8,3,1280,1280]
    const float* V   = (const float*)d_in[1];  // [8,5,256,256]
    const float* H   = (const float*)d_in[2];  // [8,5,256,256]
    float* out = (float*)d_out;                // [8,3,256,256]

    const int smem_bytes = C_ * TILE_BYTES;    // 76800
    cudaFuncSetAttribute(sepconv_tma10_kernel,
                         cudaFuncAttributeMaxDynamicSharedMemorySize,
                         smem_bytes);

    const int blocks = B_ * HO_;               // 2048: (b, y)
    sepconv_tma10_kernel<<<blocks, NT, smem_bytes>>>(in, V, H, out);
}

// round 11
// speedup vs baseline: 1.0645x; 1.0645x over previous
#include <cuda_runtime.h>
#include <cstdint>

// Sepconv: out[b,c,y,x] = sum_{i,j} in[b,c,5y+i,5x+j] * V[b,i,y,x] * H[b,j,y,x]
// B=8, C=3, F=5, HO=WO=256. HBM-bound: 184.6 MB compulsory traffic; measured
// path-independent chip ceiling ~6.15 TB/s -> ~30us kernel floor (R8 hit it).
//
// R11: R8's schedule at quarter-row granularity. 8192 blocks x 64 threads,
// 6.4KB channel strips (19.2KB smem, ~10 blocks/SM): more independent
// per-SM request streams + finer wave tail. All 3 channel strips TMA-posted
// up-front on per-channel mbarriers; consumers never issue loads.

#define B_ 8
#define C_ 3
#define F_ 5
#define HO_ 256
#define WO_ 256
#define HI_ (HO_ * F_)
#define WI_ (WO_ * F_)

#define QW_      64                       // outputs per block
#define NQ_      (WO_ / QW_)              // 4 quarters per row
#define STRIP_W  (QW_ * F_)               // 320 floats per row chunk
#define ROW_BYTES (STRIP_W * 4)           // 1280 B per bulk copy
#define TILE_FLOATS (F_ * STRIP_W)        // 1600 floats = 6.4 KB per strip
#define TILE_BYTES  (TILE_FLOATS * 4)     // 6400
#define NT QW_

__device__ __forceinline__ void mbar_init(uint32_t mbar, uint32_t count) {
    asm volatile("mbarrier.init.shared.b64 [%0], %1;\n"
                 :: "r"(mbar), "r"(count) : "memory");
}
__device__ __forceinline__ void mbar_expect_tx(uint32_t mbar, uint32_t bytes) {
    asm volatile("mbarrier.arrive.expect_tx.shared.b64 _, [%0], %1;\n"
                 :: "r"(mbar), "r"(bytes) : "memory");
}
__device__ __forceinline__ void bulk_cp(uint32_t dst, const void* src,
                                        uint32_t bytes, uint32_t mbar) {
    asm volatile(
        "cp.async.bulk.shared::cta.global.mbarrier::complete_tx::bytes "
        "[%0], [%1], %2, [%3];\n"
        :: "r"(dst), "l"(src), "r"(bytes), "r"(mbar) : "memory");
}
__device__ __forceinline__ void mbar_wait(uint32_t mbar, uint32_t parity) {
    asm volatile(
        "{\n\t"
        ".reg .pred P;\n\t"
        "WAIT_%=:\n\t"
        "mbarrier.try_wait.parity.acquire.cta.shared::cta.b64 P, [%0], %1, 0x989680;\n\t"
        "@!P bra WAIT_%=;\n\t"
        "}"
        :: "r"(mbar), "r"(parity) : "memory");
}

__global__ __launch_bounds__(NT) void sepconv_tma11_kernel(
    const float* __restrict__ in,
    const float* __restrict__ V,
    const float* __restrict__ H,
    float* __restrict__ out)
{
    __shared__ __align__(16) float sdata[C_ * TILE_FLOATS];   // 19.2 KB
    __shared__ __align__(8) unsigned long long mbar[C_];

    const int tid = threadIdx.x;                  // 0..63
    const int q   = blockIdx.x & (NQ_ - 1);       // quarter index
    const int y   = (blockIdx.x >> 2) & (HO_ - 1);
    const int b   = blockIdx.x >> 10;
    const int x0  = q * QW_;

    const uint32_t sdata_u = (uint32_t)__cvta_generic_to_shared(sdata);
    const uint32_t mbar_u  = (uint32_t)__cvta_generic_to_shared(mbar);

    if (tid == 0) {
#pragma unroll
        for (int c = 0; c < C_; c++)
            mbar_init(mbar_u + 8u * c, 1);
        asm volatile("fence.proxy.async.shared::cta;\n" ::: "memory");
    }
    __syncthreads();

    // Lanes 0..2 each post one channel's 5 bulk copies (1280 B extents).
    if (tid < C_) {
        const int c = tid;
        const long long base0 =
            ((long long)(b * C_) * HI_ + (long long)y * F_) * WI_
            + (long long)x0 * F_;
        mbar_expect_tx(mbar_u + 8u * c, TILE_BYTES);
        const float* strip = in + base0 + (long long)c * HI_ * WI_;
        const uint32_t dst = sdata_u + (uint32_t)(c * TILE_BYTES);
#pragma unroll
        for (int r = 0; r < F_; r++)
            bulk_cp(dst + (uint32_t)(r * ROW_BYTES),
                    strip + r * WI_, ROW_BYTES, mbar_u + 8u * c);
    }

    // Weights for (b, y, x0+tid): coalesced, overlap with TMA in flight.
    float v[F_], h[F_];
    {
        const int sb = (b * F_) * (HO_ * WO_) + y * WO_ + x0 + tid;
#pragma unroll
        for (int i = 0; i < F_; i++) {
            v[i] = V[sb + i * (HO_ * WO_)];
            h[i] = H[sb + i * (HO_ * WO_)];
        }
    }

#pragma unroll
    for (int c = 0; c < C_; c++) {
        mbar_wait(mbar_u + 8u * c, 0);            // acquire: strip c ready

        const float* s = sdata + c * TILE_FLOATS;
        float acc = 0.0f;
#pragma unroll
        for (int i = 0; i < F_; i++) {
            const float* row = s + i * STRIP_W + tid * F_;
            float rs = 0.0f;
#pragma unroll
            for (int j = 0; j < F_; j++)
                rs = fmaf(row[j], h[j], rs);
            acc = fmaf(rs, v[i], acc);
        }
        __stcs(out + ((b * C_ + c) * HO_ + y) * WO_ + x0 + tid, acc);
    }
}

extern "C" void kernel_launch(void* const* d_in, const int* in_sizes, int n_in,
                              void* d_out, int out_size)
{
    const float* in  = (const float*)d_in[0];  // [8,3,1280,1280]
    const float* V   = (const float*)d_in[1];  // [8,5,256,256]
    const float* H   = (const float*)d_in[2];  // [8,5,256,256]
    float* out = (float*)d_out;                // [8,3,256,256]

    const int blocks = B_ * HO_ * NQ_;         // 8192: (b, y, quarter)
    sepconv_tma11_kernel<<<blocks, NT>>>(in, V, H, out);
}